// round 7
// baseline (speedup 1.0000x reference)
#include <cuda_runtime.h>
#include <cuda_bf16.h>
#include <cstdint>

#define H 256
#define MAXROWS 50000
#define PADROWS 50048
#define LN_EPS 1e-5f

// ---------------------------------------------------------------------------
// Scratch (__device__ globals; zero-initialized at module load)
// ---------------------------------------------------------------------------
__device__ float  g_agg[MAXROWS * H];
__device__ int8_t g_aq0[PADROWS * H];
__device__ int8_t g_aq1[PADROWS * H];
__device__ int8_t g_hq0[PADROWS * H];
__device__ int8_t g_hq1[PADROWS * H];
__device__ float  g_ascale[PADROWS];
__device__ float  g_hscale[PADROWS];
__device__ int8_t g_wq[4][2][H * H];      // [which][digit][n*H+k]
__device__ float  g_wscale[4][H];

// ---------------------------------------------------------------------------
// PTX helpers
// ---------------------------------------------------------------------------
__device__ __forceinline__ uint32_t smem_u32(const void* p) {
    uint32_t a;
    asm("{ .reg .u64 t; cvta.to.shared.u64 t, %1; cvt.u32.u64 %0, t; }"
        : "=r"(a) : "l"(p));
    return a;
}
__device__ __forceinline__ void ldsm_x4(uint32_t r[4], uint32_t addr) {
    asm volatile("ldmatrix.sync.aligned.m8n8.x4.shared.b16 {%0,%1,%2,%3}, [%4];"
                 : "=r"(r[0]), "=r"(r[1]), "=r"(r[2]), "=r"(r[3]) : "r"(addr));
}
__device__ __forceinline__ void mma_s8(int c[4], const uint32_t a[4],
                                       uint32_t b0, uint32_t b1) {
    asm volatile(
        "mma.sync.aligned.m16n8k32.row.col.s32.s8.s8.s32 "
        "{%0,%1,%2,%3}, {%4,%5,%6,%7}, {%8,%9}, {%0,%1,%2,%3};"
        : "+r"(c[0]), "+r"(c[1]), "+r"(c[2]), "+r"(c[3])
        : "r"(a[0]), "r"(a[1]), "r"(a[2]), "r"(a[3]), "r"(b0), "r"(b1));
}
__device__ __forceinline__ void cp16(uint32_t dst, const void* src) {
    asm volatile("cp.async.ca.shared.global [%0], [%1], 16;"
                 :: "r"(dst), "l"(src) : "memory");
}
#define CP_COMMIT() asm volatile("cp.async.commit_group;" ::: "memory")
#define CP_WAIT0()  asm volatile("cp.async.wait_group 0;" ::: "memory")

__device__ __forceinline__ void red_v4(float* addr, float a, float b,
                                       float c, float d) {
    asm volatile("red.global.add.v4.f32 [%0], {%1,%2,%3,%4};"
                 :: "l"(addr), "f"(a), "f"(b), "f"(c), "f"(d) : "memory");
}

// ---------------------------------------------------------------------------
// SMEM layout (bytes).  A: [2 st][2 digit][64 rows x 48B].  W: [2][2][256 x 48B]
// ---------------------------------------------------------------------------
#define S_A(st, p)  ((st) * 6144 + (p) * 3072)
#define S_W(st, p)  (12288 + (st) * 24576 + (p) * 12288)
#define S_HSTG      61440                 // [2 planes][64][272]
#define S_BIAS      96256
#define S_SW        97280
#define S_G         98304
#define S_BETA      99328
#define S_HMAX      100352                // int[64]
#define S_PSUM      100608
#define S_PSQ       100864
#define SMEM_GI8    101376

// ---------------------------------------------------------------------------
// zero-fill
// ---------------------------------------------------------------------------
__global__ void zero_kernel(float4* __restrict__ p, int n4) {
    int i = blockIdx.x * blockDim.x + threadIdx.x;
    if (i < n4) p[i] = make_float4(0.f, 0.f, 0.f, 0.f);
}

// ---------------------------------------------------------------------------
// Weight prep: per output-col n (row of Wt): scale + 2 int8 digits.
// 1 warp per (weight, n). grid 128 x 256 thr.
// ---------------------------------------------------------------------------
__global__ void wprep_i8(const float* __restrict__ W0, const float* __restrict__ W1,
                         const float* __restrict__ W2, const float* __restrict__ W3,
                         int8_t* __restrict__ wq, float* __restrict__ wsc) {
    int gw = blockIdx.x * 8 + (threadIdx.x >> 5);
    int w = gw >> 8, n = gw & 255;
    int l = threadIdx.x & 31;
    const float* W = (w == 0) ? W0 : (w == 1) ? W1 : (w == 2) ? W2 : W3;

    float v[8];
#pragma unroll
    for (int j = 0; j < 8; j++) v[j] = W[(8 * l + j) * H + n];
    float m = 0.f;
#pragma unroll
    for (int j = 0; j < 8; j++) m = fmaxf(m, fabsf(v[j]));
#pragma unroll
    for (int o = 16; o > 0; o >>= 1) m = fmaxf(m, __shfl_xor_sync(~0u, m, o));
    float s, inv;
    if (m > 0.f) { s = m * (1.f / 127.f); inv = 127.f / m; }
    else         { s = 1.f; inv = 0.f; }

    char q0[8], q1[8];
#pragma unroll
    for (int j = 0; j < 8; j++) {
        float t0 = v[j] * inv;
        int a = __float2int_rn(t0);
        q0[j] = (char)a;
        q1[j] = (char)__float2int_rn((t0 - (float)a) * 254.f);
    }
    size_t base = (size_t)(w * 2) * (H * H) + n * H + 8 * l;
    *(uint64_t*)(wq + base)         = *(uint64_t*)q0;
    *(uint64_t*)(wq + base + H * H) = *(uint64_t*)q1;
    if (l == 0) wsc[w * H + n] = s;
}

// ---------------------------------------------------------------------------
// A prep: quantize A = X + AGG per row -> 2 int8 digits + scale. warp/row.
// ---------------------------------------------------------------------------
__global__ void aprep_kernel(const float* __restrict__ X, const float* __restrict__ AGG,
                             int8_t* __restrict__ q0p, int8_t* __restrict__ q1p,
                             float* __restrict__ scale, int M) {
    int r = blockIdx.x * 8 + (threadIdx.x >> 5);
    if (r >= M) return;
    int l = threadIdx.x & 31;
    const float4* xp = (const float4*)(X + (size_t)r * H + l * 8);
    const float4* gp = (const float4*)(AGG + (size_t)r * H + l * 8);
    float4 x0 = xp[0], x1 = xp[1], a0 = gp[0], a1 = gp[1];
    float v[8] = {x0.x + a0.x, x0.y + a0.y, x0.z + a0.z, x0.w + a0.w,
                  x1.x + a1.x, x1.y + a1.y, x1.z + a1.z, x1.w + a1.w};
    float m = 0.f;
#pragma unroll
    for (int j = 0; j < 8; j++) m = fmaxf(m, fabsf(v[j]));
#pragma unroll
    for (int o = 16; o > 0; o >>= 1) m = fmaxf(m, __shfl_xor_sync(~0u, m, o));
    float s, inv;
    if (m > 0.f) { s = m * (1.f / 127.f); inv = 127.f / m; }
    else         { s = 1.f; inv = 0.f; }

    char q0[8], q1[8];
#pragma unroll
    for (int j = 0; j < 8; j++) {
        float t0 = v[j] * inv;
        int a = __float2int_rn(t0);
        q0[j] = (char)a;
        q1[j] = (char)__float2int_rn((t0 - (float)a) * 254.f);
    }
    *(uint64_t*)(q0p + (size_t)r * H + 8 * l) = *(uint64_t*)q0;
    *(uint64_t*)(q1p + (size_t)r * H + 8 * l) = *(uint64_t*)q1;
    if (l == 0) scale[r] = s;
}

// ---------------------------------------------------------------------------
// Edge scatter: agg[dst] += relu(x_src[src] + ea*We + be)   (vector RED)
// ---------------------------------------------------------------------------
__global__ void edge_scatter_kernel(const float* __restrict__ xsrc,
                                    const int*  __restrict__ src,
                                    const int*  __restrict__ dst,
                                    const float* __restrict__ ea,
                                    const float* __restrict__ We,
                                    const float* __restrict__ be,
                                    float* __restrict__ agg,
                                    int Ecount) {
    int eid = blockIdx.x * 4 + (threadIdx.x >> 6);
    if (eid >= Ecount) return;
    int col = (threadIdx.x & 63) * 4;

    int s = __ldg(src + eid);
    int d = __ldg(dst + eid);
    float a = __ldg(ea + eid);

    float4 x = *(const float4*)(xsrc + (size_t)s * H + col);
    float4 w = __ldg((const float4*)(We + col));
    float4 b = __ldg((const float4*)(be + col));

    float m0 = fmaxf(x.x + fmaf(a, w.x, b.x), 0.f);
    float m1 = fmaxf(x.y + fmaf(a, w.y, b.y), 0.f);
    float m2 = fmaxf(x.z + fmaf(a, w.z, b.z), 0.f);
    float m3 = fmaxf(x.w + fmaf(a, w.w, b.w), 0.f);

    red_v4(agg + (size_t)d * H + col, m0, m1, m2, m3);
}

// ---------------------------------------------------------------------------
// int8 GEMM, tile 64M x 256N, K-chunks of 32, 512 thr (16 warps: 2m x 8n,
// warp tile 32x32). 3 int8 passes: c0 += a0*b0; cx += a1*b0; cx += a0*b1.
// C = sA_i * sW_j * (c0 + cx/254).
//   LN=false: h = relu(C + ba) -> quantized int8 digits + row scale (HQ)
//   LN=true : out = LayerNorm(C + bb + X)*g + beta
// ---------------------------------------------------------------------------
template<bool LN>
__global__ __launch_bounds__(512, 1) void gemm_i8(
    const int8_t* __restrict__ aq0, const int8_t* __restrict__ aq1,
    const float* __restrict__ ascale,
    const int8_t* __restrict__ wq0, const int8_t* __restrict__ wq1,
    const float* __restrict__ wsc,
    const float* __restrict__ bias,
    const float* __restrict__ X,           // residual (LN only)
    const float* __restrict__ gln, const float* __restrict__ bln,
    int8_t* __restrict__ hq0, int8_t* __restrict__ hq1,
    float* __restrict__ hscale,
    float* __restrict__ C, int M)
{
    extern __shared__ char sm[];
    const uint32_t sb = smem_u32(sm);

    const int t = threadIdx.x;
    const int lane = t & 31;
    const int wid = t >> 5;
    const int wm = wid & 1;       // 2 m-warps (rows 0-31 / 32-63)
    const int wn = wid >> 1;      // 8 n-warps (32 cols each)
    const int bm = blockIdx.x * 64;
    const int qrow = lane >> 2;
    const int qcol = lane & 3;

    float* biasS = (float*)(sm + S_BIAS);
    float* swS   = (float*)(sm + S_SW);
    if (t < 256) { biasS[t] = bias[t]; swS[t] = wsc[t]; }
    if (LN) {
        if (t >= 256) {
            ((float*)(sm + S_G))[t - 256]    = gln[t - 256];
            ((float*)(sm + S_BETA))[t - 256] = bln[t - 256];
        }
        if (t < 64) {
            ((float*)(sm + S_PSUM))[t] = 0.f;
            ((float*)(sm + S_PSQ))[t]  = 0.f;
        }
    } else {
        if (t < 64) ((int*)(sm + S_HMAX))[t] = 0;
    }
    // (visibility ensured by the per-chunk barriers below)

    int c0a[2][4][4], cxa[2][4][4];
#pragma unroll
    for (int i = 0; i < 2; i++)
#pragma unroll
        for (int j = 0; j < 4; j++)
#pragma unroll
            for (int e = 0; e < 4; e++) { c0a[i][j][e] = 0; cxa[i][j][e] = 0; }

    auto load_chunk = [&](int ck, int st) {
        if (t < 256) {
            int p = t >> 7, r = (t & 127) >> 1, hf = t & 1;
            const int8_t* base = p ? aq1 : aq0;
            cp16(sb + S_A(st, p) + r * 48 + hf * 16,
                 base + (size_t)(bm + r) * H + ck * 32 + hf * 16);
        }
#pragma unroll
        for (int i = 0; i < 2; i++) {
            int idx = i * 512 + t;
            int p = idx >> 9, n = (idx & 511) >> 1, hf = idx & 1;
            const int8_t* base = p ? wq1 : wq0;
            cp16(sb + S_W(st, p) + n * 48 + hf * 16,
                 base + (size_t)n * H + ck * 32 + hf * 16);
        }
    };

    const uint32_t frag_off = (uint32_t)((lane & 15) * 48 + (lane >> 4) * 16);

    load_chunk(0, 0);
    CP_COMMIT();

#pragma unroll 1
    for (int ck = 0; ck < 8; ck++) {
        const int st = ck & 1;
        CP_WAIT0();
        __syncthreads();
        if (ck < 7) { load_chunk(ck + 1, st ^ 1); CP_COMMIT(); }

        uint32_t a0f[2][4], a1f[2][4], bf[2][4];
#pragma unroll
        for (int mf = 0; mf < 2; mf++) {
            uint32_t ro = (uint32_t)((wm * 32 + mf * 16) * 48) + frag_off;
            ldsm_x4(a0f[mf], sb + S_A(st, 0) + ro);
            ldsm_x4(a1f[mf], sb + S_A(st, 1) + ro);
        }
#pragma unroll
        for (int g16 = 0; g16 < 2; g16++)
            ldsm_x4(bf[g16], sb + S_W(st, 0)
                    + (uint32_t)((wn * 32 + g16 * 16) * 48) + frag_off);
        // pass 1: c0 += a0 * b(q0)
#pragma unroll
        for (int g8 = 0; g8 < 4; g8++) {
            int g16 = g8 >> 1, pr = g8 & 1;
            mma_s8(c0a[0][g8], a0f[0], bf[g16][pr], bf[g16][2 + pr]);
            mma_s8(c0a[1][g8], a0f[1], bf[g16][pr], bf[g16][2 + pr]);
        }
        // pass 2: cx += a1 * b(q0)
#pragma unroll
        for (int g8 = 0; g8 < 4; g8++) {
            int g16 = g8 >> 1, pr = g8 & 1;
            mma_s8(cxa[0][g8], a1f[0], bf[g16][pr], bf[g16][2 + pr]);
            mma_s8(cxa[1][g8], a1f[1], bf[g16][pr], bf[g16][2 + pr]);
        }
        // reload b(q1), pass 3: cx += a0 * b(q1)
#pragma unroll
        for (int g16 = 0; g16 < 2; g16++)
            ldsm_x4(bf[g16], sb + S_W(st, 1)
                    + (uint32_t)((wn * 32 + g16 * 16) * 48) + frag_off);
#pragma unroll
        for (int g8 = 0; g8 < 4; g8++) {
            int g16 = g8 >> 1, pr = g8 & 1;
            mma_s8(cxa[0][g8], a0f[0], bf[g16][pr], bf[g16][2 + pr]);
            mma_s8(cxa[1][g8], a0f[1], bf[g16][pr], bf[g16][2 + pr]);
        }
    }

    // per-thread row scales
    float sA[2][2];
#pragma unroll
    for (int mf = 0; mf < 2; mf++)
#pragma unroll
        for (int rh = 0; rh < 2; rh++)
            sA[mf][rh] = ascale[bm + wm * 32 + mf * 16 + rh * 8 + qrow];

    if (!LN) {
        // ---- epilogue A: h = relu(C + ba); row max; quantize -> HQ ----
        int* hmaxI = (int*)(sm + S_HMAX);
#pragma unroll
        for (int mf = 0; mf < 2; mf++)
#pragma unroll
            for (int g8 = 0; g8 < 4; g8++)
#pragma unroll
                for (int e = 0; e < 4; e++) {
                    int rh = e >> 1, cc = e & 1;
                    int r = wm * 32 + mf * 16 + rh * 8 + qrow;
                    int col = wn * 32 + g8 * 8 + qcol * 2 + cc;
                    float f = (float)c0a[mf][g8][e]
                            + (float)cxa[mf][g8][e] * (1.f / 254.f);
                    float h = fmaxf(sA[mf][rh] * f * swS[col] + biasS[col], 0.f);
                    atomicMax(&hmaxI[r], __float_as_int(h));
                    c0a[mf][g8][e] = __float_as_int(h);
                }
        __syncthreads();
        float invv[2][2];
#pragma unroll
        for (int mf = 0; mf < 2; mf++)
#pragma unroll
            for (int rh = 0; rh < 2; rh++) {
                int r = wm * 32 + mf * 16 + rh * 8 + qrow;
                float hm = __int_as_float(hmaxI[r]);
                invv[mf][rh] = (hm > 0.f) ? 127.f / hm : 0.f;
                if (wn == 0 && qcol == 0)
                    hscale[bm + r] = (hm > 0.f) ? hm * (1.f / 127.f) : 1.f;
            }
#pragma unroll
        for (int mf = 0; mf < 2; mf++)
#pragma unroll
            for (int g8 = 0; g8 < 4; g8++)
#pragma unroll
                for (int rh = 0; rh < 2; rh++) {
                    float inv = invv[mf][rh];
                    float h0 = __int_as_float(c0a[mf][g8][rh * 2]);
                    float h1 = __int_as_float(c0a[mf][g8][rh * 2 + 1]);
                    float t0 = h0 * inv, t1 = h1 * inv;
                    int a0i = __float2int_rn(t0), a1i = __float2int_rn(t1);
                    int b0i = __float2int_rn((t0 - (float)a0i) * 254.f);
                    int b1i = __float2int_rn((t1 - (float)a1i) * 254.f);
                    int r = wm * 32 + mf * 16 + rh * 8 + qrow;
                    int col = wn * 32 + g8 * 8 + qcol * 2;
                    uint32_t off = (uint32_t)(r * 272 + col);
                    *(uint16_t*)(sm + S_HSTG + off) =
                        (uint16_t)((a0i & 0xFF) | ((a1i & 0xFF) << 8));
                    *(uint16_t*)(sm + S_HSTG + 17408 + off) =
                        (uint16_t)((b0i & 0xFF) | ((b1i & 0xFF) << 8));
                }
        __syncthreads();
        // coalesced copy to global digit planes
#pragma unroll
        for (int i = 0; i < 4; i++) {
            int idx = i * 512 + t;
            int p = idx >> 10, rr = (idx >> 4) & 63, sg = idx & 15;
            uint4 v = *(uint4*)(sm + S_HSTG + p * 17408 + rr * 272 + sg * 16);
            int8_t* dst = p ? hq1 : hq0;
            *(uint4*)(dst + (size_t)(bm + rr) * H + sg * 16) = v;
        }
    } else {
        // ---- epilogue B: LN(C + bb + X) * g + beta ----
        float* psum = (float*)(sm + S_PSUM);
        float* psq  = (float*)(sm + S_PSQ);
#pragma unroll
        for (int mf = 0; mf < 2; mf++)
#pragma unroll
            for (int rh = 0; rh < 2; rh++) {
                int r = wm * 32 + mf * 16 + rh * 8 + qrow;
                int grow = bm + r;
                float su = 0.f, sq = 0.f;
                if (grow < M) {
                    const float* rrow = X + (size_t)grow * H;
#pragma unroll
                    for (int g8 = 0; g8 < 4; g8++) {
                        int col = wn * 32 + g8 * 8 + qcol * 2;
                        float2 rv = *(const float2*)(rrow + col);
                        float f0 = (float)c0a[mf][g8][rh * 2]
                                 + (float)cxa[mf][g8][rh * 2] * (1.f / 254.f);
                        float f1 = (float)c0a[mf][g8][rh * 2 + 1]
                                 + (float)cxa[mf][g8][rh * 2 + 1] * (1.f / 254.f);
                        float z0 = sA[mf][rh] * f0 * swS[col]     + biasS[col]     + rv.x;
                        float z1 = sA[mf][rh] * f1 * swS[col + 1] + biasS[col + 1] + rv.y;
                        c0a[mf][g8][rh * 2]     = __float_as_int(z0);
                        c0a[mf][g8][rh * 2 + 1] = __float_as_int(z1);
                        su += z0 + z1;
                        sq += z0 * z0 + z1 * z1;
                    }
                }
                su += __shfl_xor_sync(~0u, su, 1);
                su += __shfl_xor_sync(~0u, su, 2);
                sq += __shfl_xor_sync(~0u, sq, 1);
                sq += __shfl_xor_sync(~0u, sq, 2);
                if (qcol == 0 && grow < M) {
                    atomicAdd(&psum[r], su);
                    atomicAdd(&psq[r], sq);
                }
            }
        __syncthreads();
        float* gS = (float*)(sm + S_G);
        float* bS = (float*)(sm + S_BETA);
#pragma unroll
        for (int mf = 0; mf < 2; mf++)
#pragma unroll
            for (int rh = 0; rh < 2; rh++) {
                int r = wm * 32 + mf * 16 + rh * 8 + qrow;
                int grow = bm + r;
                if (grow >= M) continue;
                float mu = psum[r] * (1.f / 256.f);
                float var = psq[r] * (1.f / 256.f) - mu * mu;
                float rs = rsqrtf(var + LN_EPS);
                float* crow = C + (size_t)grow * H;
#pragma unroll
                for (int g8 = 0; g8 < 4; g8++) {
                    int col = wn * 32 + g8 * 8 + qcol * 2;
                    float z0 = __int_as_float(c0a[mf][g8][rh * 2]);
                    float z1 = __int_as_float(c0a[mf][g8][rh * 2 + 1]);
                    float2 o;
                    o.x = (z0 - mu) * rs * gS[col]     + bS[col];
                    o.y = (z1 - mu) * rs * gS[col + 1] + bS[col + 1];
                    *(float2*)(crow + col) = o;
                }
            }
    }
}

// ---------------------------------------------------------------------------
// launch
// ---------------------------------------------------------------------------
extern "C" void kernel_launch(void* const* d_in, const int* in_sizes, int n_in,
                              void* d_out, int out_size) {
    const float* x_var    = (const float*)d_in[0];
    const float* x_constr = (const float*)d_in[1];
    const int*   ei_v2c   = (const int*)  d_in[2];
    const int*   ei_c2v   = (const int*)  d_in[3];
    const float* ea       = (const float*)d_in[4];
    const float* We1 = (const float*)d_in[5];
    const float* be1 = (const float*)d_in[6];
    const float* W1a = (const float*)d_in[7];
    const float* b1a = (const float*)d_in[8];
    const float* W1b = (const float*)d_in[9];
    const float* b1b = (const float*)d_in[10];
    const float* We2 = (const float*)d_in[11];
    const float* be2 = (const float*)d_in[12];
    const float* W2a = (const float*)d_in[13];
    const float* b2a = (const float*)d_in[14];
    const float* W2b = (const float*)d_in[15];
    const float* b2b = (const float*)d_in[16];
    const float* g_constr    = (const float*)d_in[17];
    const float* beta_constr = (const float*)d_in[18];
    const float* g_var       = (const float*)d_in[19];
    const float* beta_var    = (const float*)d_in[20];

    const int NVr = in_sizes[0] / H;
    const int NCr = in_sizes[1] / H;
    const int Ecnt = in_sizes[4];

    float *agg, *ascale, *hscale, *wsc;
    int8_t *aq0, *aq1, *hq0, *hq1, *wq;
    cudaGetSymbolAddress((void**)&agg, g_agg);
    cudaGetSymbolAddress((void**)&aq0, g_aq0);
    cudaGetSymbolAddress((void**)&aq1, g_aq1);
    cudaGetSymbolAddress((void**)&hq0, g_hq0);
    cudaGetSymbolAddress((void**)&hq1, g_hq1);
    cudaGetSymbolAddress((void**)&ascale, g_ascale);
    cudaGetSymbolAddress((void**)&hscale, g_hscale);
    cudaGetSymbolAddress((void**)&wq, g_wq);
    cudaGetSymbolAddress((void**)&wsc, g_wscale);

    int8_t* wq1a0 = wq;                   int8_t* wq1a1 = wq + H * H;
    int8_t* wq1b0 = wq + 2 * H * H;       int8_t* wq1b1 = wq + 3 * H * H;
    int8_t* wq2a0 = wq + 4 * H * H;       int8_t* wq2a1 = wq + 5 * H * H;
    int8_t* wq2b0 = wq + 6 * H * H;       int8_t* wq2b1 = wq + 7 * H * H;
    float* ws1a = wsc;        float* ws1b = wsc + H;
    float* ws2a = wsc + 2*H;  float* ws2b = wsc + 3*H;

    cudaFuncSetAttribute(gemm_i8<false>,
                         cudaFuncAttributeMaxDynamicSharedMemorySize, SMEM_GI8);
    cudaFuncSetAttribute(gemm_i8<true>,
                         cudaFuncAttributeMaxDynamicSharedMemorySize, SMEM_GI8);

    float* out_var    = (float*)d_out;
    float* out_constr = (float*)d_out + (size_t)NVr * H;

    const int edge_blocks = (Ecnt + 3) / 4;

    wprep_i8<<<128, 256>>>(W1a, W1b, W2a, W2b, wq, wsc);

    // ---- stage 1: var -> constr ----
    {
        int n4 = NCr * H / 4;
        zero_kernel<<<(n4 + 255) / 256, 256>>>((float4*)agg, n4);
        edge_scatter_kernel<<<edge_blocks, 256>>>(x_var, ei_v2c, ei_v2c + Ecnt,
                                                  ea, We1, be1, agg, Ecnt);
        aprep_kernel<<<(NCr + 7) / 8, 256>>>(x_constr, agg, aq0, aq1, ascale, NCr);
        int gx = (NCr + 63) / 64;
        gemm_i8<false><<<gx, 512, SMEM_GI8>>>(
            aq0, aq1, ascale, wq1a0, wq1a1, ws1a, b1a,
            nullptr, nullptr, nullptr, hq0, hq1, hscale, nullptr, NCr);
        gemm_i8<true><<<gx, 512, SMEM_GI8>>>(
            hq0, hq1, hscale, wq1b0, wq1b1, ws1b, b1b,
            x_constr, g_constr, beta_constr, nullptr, nullptr, nullptr,
            out_constr, NCr);
    }

    // ---- stage 2: constr -> var (reads LN'd x_constr from d_out) ----
    {
        int n4 = NVr * H / 4;
        zero_kernel<<<(n4 + 255) / 256, 256>>>((float4*)agg, n4);
        edge_scatter_kernel<<<edge_blocks, 256>>>(out_constr, ei_c2v, ei_c2v + Ecnt,
                                                  ea, We2, be2, agg, Ecnt);
        aprep_kernel<<<(NVr + 7) / 8, 256>>>(x_var, agg, aq0, aq1, ascale, NVr);
        int gx = (NVr + 63) / 64;
        gemm_i8<false><<<gx, 512, SMEM_GI8>>>(
            aq0, aq1, ascale, wq2a0, wq2a1, ws2a, b2a,
            nullptr, nullptr, nullptr, hq0, hq1, hscale, nullptr, NVr);
        gemm_i8<true><<<gx, 512, SMEM_GI8>>>(
            hq0, hq1, hscale, wq2b0, wq2b1, ws2b, b2b,
            x_var, g_var, beta_var, nullptr, nullptr, nullptr,
            out_var, NVr);
    }
}

// round 8
// speedup vs baseline: 1.8252x; 1.8252x over previous
#include <cuda_runtime.h>
#include <cuda_fp16.h>
#include <cstdint>

#define H 256
#define MAXROWS 50000
#define LN_EPS 1e-5f

// ---------------------------------------------------------------------------
// Scratch (__device__ globals: allocation-free rule)
// ---------------------------------------------------------------------------
__device__ float g_agg[MAXROWS * H];
// Transposed weights, single fp16 digit: [which 0..3][n*H + k]
__device__ __half g_wt[4][H * H];

// ---------------------------------------------------------------------------
// PTX helpers
// ---------------------------------------------------------------------------
__device__ __forceinline__ uint32_t smem_u32(const void* p) {
    uint32_t a;
    asm("{ .reg .u64 t; cvta.to.shared.u64 t, %1; cvt.u32.u64 %0, t; }"
        : "=r"(a) : "l"(p));
    return a;
}
__device__ __forceinline__ void ldsm_x4(uint32_t r[4], uint32_t addr) {
    asm volatile("ldmatrix.sync.aligned.m8n8.x4.shared.b16 {%0,%1,%2,%3}, [%4];"
                 : "=r"(r[0]), "=r"(r[1]), "=r"(r[2]), "=r"(r[3]) : "r"(addr));
}
__device__ __forceinline__ void mma_f16(float c[4],
                                        const uint32_t a[4],
                                        uint32_t b0, uint32_t b1) {
    asm volatile(
        "mma.sync.aligned.m16n8k16.row.col.f32.f16.f16.f32 "
        "{%0,%1,%2,%3}, {%4,%5,%6,%7}, {%8,%9}, {%0,%1,%2,%3};"
        : "+f"(c[0]), "+f"(c[1]), "+f"(c[2]), "+f"(c[3])
        : "r"(a[0]), "r"(a[1]), "r"(a[2]), "r"(a[3]), "r"(b0), "r"(b1));
}
__device__ __forceinline__ void cp16(uint32_t dst, const void* src) {
    asm volatile("cp.async.ca.shared.global [%0], [%1], 16;"
                 :: "r"(dst), "l"(src) : "memory");
}
#define CP_COMMIT() asm volatile("cp.async.commit_group;" ::: "memory")
#define CP_WAIT1()  asm volatile("cp.async.wait_group 1;" ::: "memory")
#define CP_WAIT0()  asm volatile("cp.async.wait_group 0;" ::: "memory")

__device__ __forceinline__ void red_v4(float* addr, float a, float b,
                                       float c, float d) {
    asm volatile("red.global.add.v4.f32 [%0], {%1,%2,%3,%4};"
                 :: "l"(addr), "f"(a), "f"(b), "f"(c), "f"(d) : "memory");
}
__device__ __forceinline__ uint32_t pack2h(float a, float b) {
    __half2 h = __floats2half2_rn(a, b);
    return *(uint32_t*)&h;
}

// ---------------------------------------------------------------------------
// SMEM layout (bytes)
//   A chunk: [64 rows][40 fp16] (80B stride), hi + lo digits, 2 stages.
//   W chunk: [256 n][40 fp16], single digit, 2 stages.
//   h (intermediate): 8 chunks x [64][40] fp16, hi + lo planes.
// ---------------------------------------------------------------------------
#define SM_A(st)   ((st) * 10240)          // hi at +0, lo at +5120
#define SM_A_LO    5120
#define SM_W(st)   (20480 + (st) * 20480)
#define SM_H       61440                   // hi: 8*5120; lo at +40960
#define SM_H_LO    40960
#define SM_B1      143360
#define SM_B2      144384
#define SM_G       145408
#define SM_BETA    146432
#define SM_PSUM    147456
#define SM_PSQ     147712
#define SMEM_T     147968

// ---------------------------------------------------------------------------
// zero-fill
// ---------------------------------------------------------------------------
__global__ void zero_kernel(float4* __restrict__ p, int n4) {
    int i = blockIdx.x * blockDim.x + threadIdx.x;
    if (i < n4) p[i] = make_float4(0.f, 0.f, 0.f, 0.f);
}

// ---------------------------------------------------------------------------
// Weight prep (4 weights, one launch): Wt[n][k] = fp16(W[k][n])
// ---------------------------------------------------------------------------
__global__ void wprep4_kernel(const float* __restrict__ W0,
                              const float* __restrict__ W1,
                              const float* __restrict__ W2,
                              const float* __restrict__ W3,
                              __half* __restrict__ base) {
    __shared__ float tile[32][33];
    const int which = blockIdx.x >> 6;
    const float* W = (which == 0) ? W0 : (which == 1) ? W1
                   : (which == 2) ? W2 : W3;
    __half* hi = base + (size_t)which * H * H;
    const int b  = blockIdx.x & 63;
    const int tx = threadIdx.x & 31;
    const int ty = threadIdx.x >> 5;
    const int bx = b & 7;
    const int by = b >> 3;
#pragma unroll
    for (int i = 0; i < 4; i++)
        tile[ty + i * 8][tx] = W[(by * 32 + ty + i * 8) * H + bx * 32 + tx];
    __syncthreads();
#pragma unroll
    for (int i = 0; i < 4; i++) {
        float v = tile[tx][ty + i * 8];
        int n = bx * 32 + ty + i * 8;
        int k = by * 32 + tx;
        hi[n * H + k] = __float2half_rn(v);
    }
}

// ---------------------------------------------------------------------------
// Edge scatter: agg[dst] += relu(x_src[src] + ea*We + be)   (vector RED)
// ---------------------------------------------------------------------------
__global__ void edge_scatter_kernel(const float* __restrict__ xsrc,
                                    const int*  __restrict__ src,
                                    const int*  __restrict__ dst,
                                    const float* __restrict__ ea,
                                    const float* __restrict__ We,
                                    const float* __restrict__ be,
                                    float* __restrict__ agg,
                                    int Ecount) {
    int eid = blockIdx.x * 4 + (threadIdx.x >> 6);
    if (eid >= Ecount) return;
    int col = (threadIdx.x & 63) * 4;

    int s = __ldg(src + eid);
    int d = __ldg(dst + eid);
    float a = __ldg(ea + eid);

    float4 x = *(const float4*)(xsrc + (size_t)s * H + col);
    float4 w = __ldg((const float4*)(We + col));
    float4 b = __ldg((const float4*)(be + col));

    float m0 = fmaxf(x.x + fmaf(a, w.x, b.x), 0.f);
    float m1 = fmaxf(x.y + fmaf(a, w.y, b.y), 0.f);
    float m2 = fmaxf(x.z + fmaf(a, w.z, b.z), 0.f);
    float m3 = fmaxf(x.w + fmaf(a, w.w, b.w), 0.f);

    red_v4(agg + (size_t)d * H + col, m0, m1, m2, m3);
}

// ---------------------------------------------------------------------------
// Fused GINE MLP: out = LN( relu((x+agg)@Wa + ba) @ Wb + bb + x ) * g + beta
// fp16 2-pass: A in two fp16 digits, W single fp16 digit -> C = A @ fp16(W).
// Tile: 64M x 256N, BK=32, 8 warps (2m x 4n), double-buffered W via cp.async.
// ---------------------------------------------------------------------------
__global__ __launch_bounds__(256) void fused_gine(
    const float* __restrict__ X, const float* __restrict__ AGG,
    const __half* __restrict__ Wa, const __half* __restrict__ Wb,
    const float* __restrict__ ba, const float* __restrict__ bb,
    const float* __restrict__ gln, const float* __restrict__ bln,
    float* __restrict__ C, int M)
{
    extern __shared__ char sm[];
    const uint32_t sb = smem_u32(sm);

    const int t = threadIdx.x;
    const int lane = t & 31;
    const int wid = t >> 5;
    const int wm = wid & 1;       // 2 m-warps
    const int wn = wid >> 1;      // 4 n-warps
    const int bm = blockIdx.x * 64;

    float* b1S  = (float*)(sm + SM_B1);
    float* b2S  = (float*)(sm + SM_B2);
    float* gS   = (float*)(sm + SM_G);
    float* bS   = (float*)(sm + SM_BETA);
    float* psum = (float*)(sm + SM_PSUM);
    float* psq  = (float*)(sm + SM_PSQ);

    b1S[t] = ba[t];
    b2S[t] = bb[t];
    gS[t]  = gln[t];
    bS[t]  = bln[t];
    if (t < 64) { psum[t] = 0.f; psq[t] = 0.f; }

    float c[2][8][4];
#pragma unroll
    for (int i = 0; i < 2; i++)
#pragma unroll
        for (int j = 0; j < 8; j++)
#pragma unroll
            for (int e = 0; e < 4; e++) c[i][j][e] = 0.f;

    const int row_a = t >> 2;
    const int kq_a  = t & 3;
    const int grow_a = bm + row_a;
    const bool aval = (grow_a < M);

    auto lda = [&](int ck, float4& v0, float4& v1) {
        if (aval) {
            size_t off = (size_t)grow_a * H + ck * 32 + kq_a * 8;
            const float4* p = (const float4*)(X + off);
            const float4* q = (const float4*)(AGG + off);
            float4 a0 = p[0], a1 = p[1];
            float4 u0 = q[0], u1 = q[1];
            v0.x = a0.x + u0.x; v0.y = a0.y + u0.y;
            v0.z = a0.z + u0.z; v0.w = a0.w + u0.w;
            v1.x = a1.x + u1.x; v1.y = a1.y + u1.y;
            v1.z = a1.z + u1.z; v1.w = a1.w + u1.w;
        } else {
            v0 = make_float4(0.f, 0.f, 0.f, 0.f);
            v1 = v0;
        }
    };
    auto sts_a = [&](int st, float4 v0, float4 v1) {
        float x[8] = {v0.x, v0.y, v0.z, v0.w, v1.x, v1.y, v1.z, v1.w};
        uint32_t hv[4], lv[4];
#pragma unroll
        for (int j = 0; j < 4; j++) {
            __half h0 = __float2half_rn(x[2*j]);
            __half h1 = __float2half_rn(x[2*j+1]);
            float l0 = x[2*j]   - __half2float(h0);
            float l1 = x[2*j+1] - __half2float(h1);
            hv[j] = pack2h(__half2float(h0), __half2float(h1));
            lv[j] = pack2h(l0, l1);
        }
        uint32_t o = (uint32_t)(row_a * 80 + kq_a * 16);
        *(uint4*)(sm + SM_A(st) + o) = make_uint4(hv[0], hv[1], hv[2], hv[3]);
        *(uint4*)(sm + SM_A(st) + SM_A_LO + o) = make_uint4(lv[0], lv[1], lv[2], lv[3]);
    };
    auto cpw = [&](const __half* W, int ck, int st) {
        const __half* s = W + (size_t)t * H + ck * 32;
        uint32_t d = sb + SM_W(st) + t * 80;
#pragma unroll
        for (int q = 0; q < 4; q++) cp16(d + q * 16, s + q * 8);
    };

    const uint32_t a_off = (uint32_t)((lane & 15) * 80 + (lane >> 4) * 16);
    const uint32_t w_off = (uint32_t)((wn * 64 + (lane & 7) + ((lane >> 4) * 8)) * 80
                                      + (((lane >> 3) & 1) * 16));

    // 2-pass MMA over a 32-K chunk: pass1 Ah*W, pass2 Al*W.
    auto compute = [&](uint32_t aBase, uint32_t aLoDelta, uint32_t wBase) {
        const uint32_t ah_base = aBase + (uint32_t)(wm * 2560) + a_off;
        const uint32_t wh_base = wBase + w_off;
#pragma unroll
        for (int ks = 0; ks < 2; ks++) {
            uint32_t ah0[4], ah1[4], al0[4], al1[4];
            uint32_t ab = ah_base + ks * 32;
            ldsm_x4(ah0, ab);
            ldsm_x4(ah1, ab + 1280);
            ldsm_x4(al0, ab + aLoDelta);
            ldsm_x4(al1, ab + aLoDelta + 1280);
            uint32_t bf[4][4];
            uint32_t wb = wh_base + ks * 32;
#pragma unroll
            for (int n4 = 0; n4 < 4; n4++) ldsm_x4(bf[n4], wb + n4 * 1280);
            // pass 1: Ah * W
#pragma unroll
            for (int n4 = 0; n4 < 4; n4++) {
                const int nf = n4 * 2;
                mma_f16(c[0][nf],     ah0, bf[n4][0], bf[n4][1]);
                mma_f16(c[0][nf + 1], ah0, bf[n4][2], bf[n4][3]);
                mma_f16(c[1][nf],     ah1, bf[n4][0], bf[n4][1]);
                mma_f16(c[1][nf + 1], ah1, bf[n4][2], bf[n4][3]);
            }
            // pass 2: Al * W
#pragma unroll
            for (int n4 = 0; n4 < 4; n4++) {
                const int nf = n4 * 2;
                mma_f16(c[0][nf],     al0, bf[n4][0], bf[n4][1]);
                mma_f16(c[0][nf + 1], al0, bf[n4][2], bf[n4][3]);
                mma_f16(c[1][nf],     al1, bf[n4][0], bf[n4][1]);
                mma_f16(c[1][nf + 1], al1, bf[n4][2], bf[n4][3]);
            }
        }
    };

    const int qrow = lane >> 2;
    const int qcol = lane & 3;

    // =================== Phase A: acc1 = (X+AGG) @ Wa ===================
    float4 p0, p1, n0, n1;
    lda(0, p0, p1);
    cpw(Wa, 0, 0);
    CP_COMMIT();

#pragma unroll 1
    for (int ck = 0; ck < 8; ck++) {
        const int st = ck & 1;
        sts_a(st, p0, p1);
        if (ck < 7) {
            lda(ck + 1, n0, n1);
            cpw(Wa, ck + 1, st ^ 1);
            CP_COMMIT();
            CP_WAIT1();
        } else {
            CP_WAIT0();
        }
        __syncthreads();
        compute(sb + SM_A(st), SM_A_LO, sb + SM_W(st));
        __syncthreads();
        p0 = n0; p1 = n1;
    }

    // ---- epilogue 1: h = relu(acc1 + ba) -> smem fp16 hi/lo (A layout) ----
#pragma unroll
    for (int mf = 0; mf < 2; mf++)
#pragma unroll
        for (int rh = 0; rh < 2; rh++) {
            int r = wm * 32 + mf * 16 + rh * 8 + qrow;
#pragma unroll
            for (int nf = 0; nf < 8; nf++) {
                int kcol = wn * 64 + nf * 8 + qcol * 2;
                float z0 = fmaxf(c[mf][nf][rh * 2]     + b1S[kcol],     0.f);
                float z1 = fmaxf(c[mf][nf][rh * 2 + 1] + b1S[kcol + 1], 0.f);
                __half h0 = __float2half_rn(z0);
                __half h1 = __float2half_rn(z1);
                float l0 = z0 - __half2float(h0);
                float l1 = z1 - __half2float(h1);
                uint32_t off = (uint32_t)((kcol >> 5) * 5120 + r * 80
                                          + (kcol & 31) * 2);
                *(uint32_t*)(sm + SM_H + off) =
                    pack2h(__half2float(h0), __half2float(h1));
                *(uint32_t*)(sm + SM_H + SM_H_LO + off) = pack2h(l0, l1);
            }
        }

    // zero accumulators for phase B
#pragma unroll
    for (int i = 0; i < 2; i++)
#pragma unroll
        for (int j = 0; j < 8; j++)
#pragma unroll
            for (int e = 0; e < 4; e++) c[i][j][e] = 0.f;

    // =================== Phase B: acc2 = h @ Wb =========================
    cpw(Wb, 0, 0);
    CP_COMMIT();

#pragma unroll 1
    for (int ck = 0; ck < 8; ck++) {
        const int st = ck & 1;
        if (ck < 7) {
            cpw(Wb, ck + 1, st ^ 1);
            CP_COMMIT();
            CP_WAIT1();
        } else {
            CP_WAIT0();
        }
        __syncthreads();
        compute(sb + SM_H + ck * 5120, SM_H_LO, sb + SM_W(st));
        __syncthreads();
    }

    // ---- epilogue 2: LN(acc2 + bb + X) * g + beta ----
#pragma unroll
    for (int mf = 0; mf < 2; mf++)
#pragma unroll
        for (int rh = 0; rh < 2; rh++) {
            int r = wm * 32 + mf * 16 + rh * 8 + qrow;
            int grow = bm + r;
            float su = 0.f, sq = 0.f;
            if (grow < M) {
                const float* rrow = X + (size_t)grow * H;
#pragma unroll
                for (int nf = 0; nf < 8; nf++) {
                    int col = wn * 64 + nf * 8 + qcol * 2;
                    float2 rv = *(const float2*)(rrow + col);
                    float z0 = c[mf][nf][rh * 2]     + b2S[col]     + rv.x;
                    float z1 = c[mf][nf][rh * 2 + 1] + b2S[col + 1] + rv.y;
                    c[mf][nf][rh * 2]     = z0;
                    c[mf][nf][rh * 2 + 1] = z1;
                    su += z0 + z1;
                    sq += z0 * z0 + z1 * z1;
                }
            }
            su += __shfl_xor_sync(0xFFFFFFFFu, su, 1);
            su += __shfl_xor_sync(0xFFFFFFFFu, su, 2);
            sq += __shfl_xor_sync(0xFFFFFFFFu, sq, 1);
            sq += __shfl_xor_sync(0xFFFFFFFFu, sq, 2);
            if (qcol == 0 && grow < M) {
                atomicAdd(&psum[r], su);
                atomicAdd(&psq[r], sq);
            }
        }
    __syncthreads();
#pragma unroll
    for (int mf = 0; mf < 2; mf++)
#pragma unroll
        for (int rh = 0; rh < 2; rh++) {
            int r = wm * 32 + mf * 16 + rh * 8 + qrow;
            int grow = bm + r;
            if (grow >= M) continue;
            float mu = psum[r] * (1.f / 256.f);
            float var = psq[r] * (1.f / 256.f) - mu * mu;
            float rs = rsqrtf(var + LN_EPS);
            float* crow = C + (size_t)grow * H;
#pragma unroll
            for (int nf = 0; nf < 8; nf++) {
                int col = wn * 64 + nf * 8 + qcol * 2;
                float2 o;
                o.x = (c[mf][nf][rh * 2]     - mu) * rs * gS[col]     + bS[col];
                o.y = (c[mf][nf][rh * 2 + 1] - mu) * rs * gS[col + 1] + bS[col + 1];
                *(float2*)(crow + col) = o;
            }
        }
}

// ---------------------------------------------------------------------------
// launch
// ---------------------------------------------------------------------------
extern "C" void kernel_launch(void* const* d_in, const int* in_sizes, int n_in,
                              void* d_out, int out_size) {
    const float* x_var    = (const float*)d_in[0];
    const float* x_constr = (const float*)d_in[1];
    const int*   ei_v2c   = (const int*)  d_in[2];
    const int*   ei_c2v   = (const int*)  d_in[3];
    const float* ea       = (const float*)d_in[4];
    const float* We1 = (const float*)d_in[5];
    const float* be1 = (const float*)d_in[6];
    const float* W1a = (const float*)d_in[7];
    const float* b1a = (const float*)d_in[8];
    const float* W1b = (const float*)d_in[9];
    const float* b1b = (const float*)d_in[10];
    const float* We2 = (const float*)d_in[11];
    const float* be2 = (const float*)d_in[12];
    const float* W2a = (const float*)d_in[13];
    const float* b2a = (const float*)d_in[14];
    const float* W2b = (const float*)d_in[15];
    const float* b2b = (const float*)d_in[16];
    const float* g_constr    = (const float*)d_in[17];
    const float* beta_constr = (const float*)d_in[18];
    const float* g_var       = (const float*)d_in[19];
    const float* beta_var    = (const float*)d_in[20];

    const int NVr = in_sizes[0] / H;
    const int NCr = in_sizes[1] / H;
    const int Ecnt = in_sizes[4];

    float* agg;
    cudaGetSymbolAddress((void**)&agg, g_agg);
    __half* wt;
    cudaGetSymbolAddress((void**)&wt, g_wt);
    __half* wt1a = wt;
    __half* wt1b = wt + H * H;
    __half* wt2a = wt + 2 * H * H;
    __half* wt2b = wt + 3 * H * H;

    cudaFuncSetAttribute(fused_gine,
                         cudaFuncAttributeMaxDynamicSharedMemorySize, SMEM_T);

    float* out_var    = (float*)d_out;
    float* out_constr = (float*)d_out + (size_t)NVr * H;

    const int edge_blocks = (Ecnt + 3) / 4;

    // weight prep: all 4 weights (order: W1a, W1b, W2a, W2b)
    wprep4_kernel<<<256, 256>>>(W1a, W1b, W2a, W2b, wt);

    // ---- stage 1: var -> constr ----
    {
        int n4 = NCr * H / 4;
        zero_kernel<<<(n4 + 255) / 256, 256>>>((float4*)agg, n4);
        edge_scatter_kernel<<<edge_blocks, 256>>>(x_var, ei_v2c, ei_v2c + Ecnt,
                                                  ea, We1, be1, agg, Ecnt);
        int gx = (NCr + 63) / 64;
        fused_gine<<<gx, 256, SMEM_T>>>(
            x_constr, agg, wt1a, wt1b, b1a, b1b,
            g_constr, beta_constr, out_constr, NCr);
    }

    // ---- stage 2: constr -> var (reads LN'd x_constr from d_out) ----
    {
        int n4 = NVr * H / 4;
        zero_kernel<<<(n4 + 255) / 256, 256>>>((float4*)agg, n4);
        edge_scatter_kernel<<<edge_blocks, 256>>>(out_constr, ei_c2v, ei_c2v + Ecnt,
                                                  ea, We2, be2, agg, Ecnt);
        int gx = (NVr + 63) / 64;
        fused_gine<<<gx, 256, SMEM_T>>>(
            x_var, agg, wt2a, wt2b, b2a, b2b,
            g_var, beta_var, out_var, NVr);
    }
}

// round 9
// speedup vs baseline: 2.3209x; 1.2715x over previous
#include <cuda_runtime.h>
#include <cuda_fp16.h>
#include <cstdint>

#define H 256
#define MAXROWS 50000
#define LN_EPS 1e-5f

// ---------------------------------------------------------------------------
// Scratch (__device__ globals: allocation-free rule)
// ---------------------------------------------------------------------------
__device__ float g_agg[MAXROWS * H];
// Transposed weights, single fp16: [which 0..3][n*H + k]
__device__ __half g_wt[4][H * H];

// ---------------------------------------------------------------------------
// PTX helpers
// ---------------------------------------------------------------------------
__device__ __forceinline__ uint32_t smem_u32(const void* p) {
    uint32_t a;
    asm("{ .reg .u64 t; cvta.to.shared.u64 t, %1; cvt.u32.u64 %0, t; }"
        : "=r"(a) : "l"(p));
    return a;
}
__device__ __forceinline__ void ldsm_x4(uint32_t r[4], uint32_t addr) {
    asm volatile("ldmatrix.sync.aligned.m8n8.x4.shared.b16 {%0,%1,%2,%3}, [%4];"
                 : "=r"(r[0]), "=r"(r[1]), "=r"(r[2]), "=r"(r[3]) : "r"(addr));
}
__device__ __forceinline__ void mma_f16(float c[4],
                                        const uint32_t a[4],
                                        uint32_t b0, uint32_t b1) {
    asm volatile(
        "mma.sync.aligned.m16n8k16.row.col.f32.f16.f16.f32 "
        "{%0,%1,%2,%3}, {%4,%5,%6,%7}, {%8,%9}, {%0,%1,%2,%3};"
        : "+f"(c[0]), "+f"(c[1]), "+f"(c[2]), "+f"(c[3])
        : "r"(a[0]), "r"(a[1]), "r"(a[2]), "r"(a[3]), "r"(b0), "r"(b1));
}
__device__ __forceinline__ void cp16(uint32_t dst, const void* src) {
    asm volatile("cp.async.ca.shared.global [%0], [%1], 16;"
                 :: "r"(dst), "l"(src) : "memory");
}
#define CP_COMMIT() asm volatile("cp.async.commit_group;" ::: "memory")
#define CP_WAIT1()  asm volatile("cp.async.wait_group 1;" ::: "memory")
#define CP_WAIT0()  asm volatile("cp.async.wait_group 0;" ::: "memory")

__device__ __forceinline__ void red_v4(float* addr, float a, float b,
                                       float c, float d) {
    asm volatile("red.global.add.v4.f32 [%0], {%1,%2,%3,%4};"
                 :: "l"(addr), "f"(a), "f"(b), "f"(c), "f"(d) : "memory");
}
__device__ __forceinline__ uint32_t pack2h(float a, float b) {
    __half2 h = __floats2half2_rn(a, b);
    return *(uint32_t*)&h;
}

// ---------------------------------------------------------------------------
// SMEM layout (bytes)
//   A chunk: [64 rows][40 fp16] (80B stride), single digit, 2 stages.
//   W chunk: [256 n][40 fp16] (80B stride), single digit, 2 stages.
//   h (intermediate): 8 chunks x [64][40] fp16, single plane.
// ---------------------------------------------------------------------------
#define SM_A(st)   ((st) * 5120)
#define SM_W(st)   (10240 + (st) * 20480)
#define SM_H       51200
#define SM_B1      92160
#define SM_B2      93184
#define SM_G       94208
#define SM_BETA    95232
#define SM_PSUM    96256
#define SM_PSQ     96512
#define SMEM_T     96768

// ---------------------------------------------------------------------------
// zero-fill
// ---------------------------------------------------------------------------
__global__ void zero_kernel(float4* __restrict__ p, int n4) {
    int i = blockIdx.x * blockDim.x + threadIdx.x;
    if (i < n4) p[i] = make_float4(0.f, 0.f, 0.f, 0.f);
}

// ---------------------------------------------------------------------------
// Weight prep (4 weights, one launch): Wt[n][k] = fp16(W[k][n])
// ---------------------------------------------------------------------------
__global__ void wprep4_kernel(const float* __restrict__ W0,
                              const float* __restrict__ W1,
                              const float* __restrict__ W2,
                              const float* __restrict__ W3,
                              __half* __restrict__ base) {
    __shared__ float tile[32][33];
    const int which = blockIdx.x >> 6;
    const float* W = (which == 0) ? W0 : (which == 1) ? W1
                   : (which == 2) ? W2 : W3;
    __half* hi = base + (size_t)which * H * H;
    const int b  = blockIdx.x & 63;
    const int tx = threadIdx.x & 31;
    const int ty = threadIdx.x >> 5;
    const int bx = b & 7;
    const int by = b >> 3;
#pragma unroll
    for (int i = 0; i < 4; i++)
        tile[ty + i * 8][tx] = W[(by * 32 + ty + i * 8) * H + bx * 32 + tx];
    __syncthreads();
#pragma unroll
    for (int i = 0; i < 4; i++) {
        float v = tile[tx][ty + i * 8];
        int n = bx * 32 + ty + i * 8;
        int k = by * 32 + tx;
        hi[n * H + k] = __float2half_rn(v);
    }
}

// ---------------------------------------------------------------------------
// Edge scatter: agg[dst] += relu(x_src[src] + ea*We + be)   (vector RED)
// ---------------------------------------------------------------------------
__global__ void edge_scatter_kernel(const float* __restrict__ xsrc,
                                    const int*  __restrict__ src,
                                    const int*  __restrict__ dst,
                                    const float* __restrict__ ea,
                                    const float* __restrict__ We,
                                    const float* __restrict__ be,
                                    float* __restrict__ agg,
                                    int Ecount) {
    int eid = blockIdx.x * 4 + (threadIdx.x >> 6);
    if (eid >= Ecount) return;
    int col = (threadIdx.x & 63) * 4;

    int s = __ldg(src + eid);
    int d = __ldg(dst + eid);
    float a = __ldg(ea + eid);

    float4 x = *(const float4*)(xsrc + (size_t)s * H + col);
    float4 w = __ldg((const float4*)(We + col));
    float4 b = __ldg((const float4*)(be + col));

    float m0 = fmaxf(x.x + fmaf(a, w.x, b.x), 0.f);
    float m1 = fmaxf(x.y + fmaf(a, w.y, b.y), 0.f);
    float m2 = fmaxf(x.z + fmaf(a, w.z, b.z), 0.f);
    float m3 = fmaxf(x.w + fmaf(a, w.w, b.w), 0.f);

    red_v4(agg + (size_t)d * H + col, m0, m1, m2, m3);
}

// ---------------------------------------------------------------------------
// Fused GINE MLP: out = LN( relu((x+agg)@Wa + ba) @ Wb + bb + x ) * g + beta
// Pure fp16 single-pass MMA (A and W both single fp16 digit).
// Tile: 64M x 256N, BK=32, 8 warps (2m x 4n), 2 CTAs/SM.
// ---------------------------------------------------------------------------
__global__ __launch_bounds__(256, 2) void fused_gine(
    const float* __restrict__ X, const float* __restrict__ AGG,
    const __half* __restrict__ Wa, const __half* __restrict__ Wb,
    const float* __restrict__ ba, const float* __restrict__ bb,
    const float* __restrict__ gln, const float* __restrict__ bln,
    float* __restrict__ C, int M)
{
    extern __shared__ char sm[];
    const uint32_t sb = smem_u32(sm);

    const int t = threadIdx.x;
    const int lane = t & 31;
    const int wid = t >> 5;
    const int wm = wid & 1;       // 2 m-warps
    const int wn = wid >> 1;      // 4 n-warps
    const int bm = blockIdx.x * 64;

    float* b1S  = (float*)(sm + SM_B1);
    float* b2S  = (float*)(sm + SM_B2);
    float* gS   = (float*)(sm + SM_G);
    float* bS   = (float*)(sm + SM_BETA);
    float* psum = (float*)(sm + SM_PSUM);
    float* psq  = (float*)(sm + SM_PSQ);

    b1S[t] = ba[t];
    b2S[t] = bb[t];
    gS[t]  = gln[t];
    bS[t]  = bln[t];
    if (t < 64) { psum[t] = 0.f; psq[t] = 0.f; }

    float c[2][8][4];
#pragma unroll
    for (int i = 0; i < 2; i++)
#pragma unroll
        for (int j = 0; j < 8; j++)
#pragma unroll
            for (int e = 0; e < 4; e++) c[i][j][e] = 0.f;

    const int row_a = t >> 2;
    const int kq_a  = t & 3;
    const int grow_a = bm + row_a;
    const bool aval = (grow_a < M);

    auto lda = [&](int ck, float4& v0, float4& v1) {
        if (aval) {
            size_t off = (size_t)grow_a * H + ck * 32 + kq_a * 8;
            const float4* p = (const float4*)(X + off);
            const float4* q = (const float4*)(AGG + off);
            float4 a0 = p[0], a1 = p[1];
            float4 u0 = q[0], u1 = q[1];
            v0.x = a0.x + u0.x; v0.y = a0.y + u0.y;
            v0.z = a0.z + u0.z; v0.w = a0.w + u0.w;
            v1.x = a1.x + u1.x; v1.y = a1.y + u1.y;
            v1.z = a1.z + u1.z; v1.w = a1.w + u1.w;
        } else {
            v0 = make_float4(0.f, 0.f, 0.f, 0.f);
            v1 = v0;
        }
    };
    auto sts_a = [&](int st, float4 v0, float4 v1) {
        uint32_t hv[4];
        hv[0] = pack2h(v0.x, v0.y);
        hv[1] = pack2h(v0.z, v0.w);
        hv[2] = pack2h(v1.x, v1.y);
        hv[3] = pack2h(v1.z, v1.w);
        uint32_t o = (uint32_t)(row_a * 80 + kq_a * 16);
        *(uint4*)(sm + SM_A(st) + o) = make_uint4(hv[0], hv[1], hv[2], hv[3]);
    };
    auto cpw = [&](const __half* W, int ck, int st) {
        const __half* s = W + (size_t)t * H + ck * 32;
        uint32_t d = sb + SM_W(st) + t * 80;
#pragma unroll
        for (int q = 0; q < 4; q++) cp16(d + q * 16, s + q * 8);
    };

    const uint32_t a_off = (uint32_t)((lane & 15) * 80 + (lane >> 4) * 16);
    const uint32_t w_off = (uint32_t)((wn * 64 + (lane & 7) + ((lane >> 4) * 8)) * 80
                                      + (((lane >> 3) & 1) * 16));

    // single-pass MMA over a 32-K chunk
    auto compute = [&](uint32_t aBase, uint32_t wBase) {
        const uint32_t ah_base = aBase + (uint32_t)(wm * 2560) + a_off;
        const uint32_t wh_base = wBase + w_off;
#pragma unroll
        for (int ks = 0; ks < 2; ks++) {
            uint32_t ah0[4], ah1[4];
            uint32_t ab = ah_base + ks * 32;
            ldsm_x4(ah0, ab);
            ldsm_x4(ah1, ab + 1280);
            uint32_t bf[4][4];
            uint32_t wb = wh_base + ks * 32;
#pragma unroll
            for (int n4 = 0; n4 < 4; n4++) ldsm_x4(bf[n4], wb + n4 * 1280);
#pragma unroll
            for (int n4 = 0; n4 < 4; n4++) {
                const int nf = n4 * 2;
                mma_f16(c[0][nf],     ah0, bf[n4][0], bf[n4][1]);
                mma_f16(c[0][nf + 1], ah0, bf[n4][2], bf[n4][3]);
                mma_f16(c[1][nf],     ah1, bf[n4][0], bf[n4][1]);
                mma_f16(c[1][nf + 1], ah1, bf[n4][2], bf[n4][3]);
            }
        }
    };

    const int qrow = lane >> 2;
    const int qcol = lane & 3;

    // =================== Phase A: acc1 = (X+AGG) @ Wa ===================
    float4 p0, p1, n0, n1;
    lda(0, p0, p1);
    cpw(Wa, 0, 0);
    CP_COMMIT();

#pragma unroll 1
    for (int ck = 0; ck < 8; ck++) {
        const int st = ck & 1;
        sts_a(st, p0, p1);
        if (ck < 7) {
            lda(ck + 1, n0, n1);
            cpw(Wa, ck + 1, st ^ 1);
            CP_COMMIT();
            CP_WAIT1();
        } else {
            CP_WAIT0();
        }
        __syncthreads();
        compute(sb + SM_A(st), sb + SM_W(st));
        __syncthreads();
        p0 = n0; p1 = n1;
    }

    // ---- epilogue 1: h = relu(acc1 + ba) -> smem fp16 (A layout) ----
#pragma unroll
    for (int mf = 0; mf < 2; mf++)
#pragma unroll
        for (int rh = 0; rh < 2; rh++) {
            int r = wm * 32 + mf * 16 + rh * 8 + qrow;
#pragma unroll
            for (int nf = 0; nf < 8; nf++) {
                int kcol = wn * 64 + nf * 8 + qcol * 2;
                float z0 = fmaxf(c[mf][nf][rh * 2]     + b1S[kcol],     0.f);
                float z1 = fmaxf(c[mf][nf][rh * 2 + 1] + b1S[kcol + 1], 0.f);
                uint32_t off = (uint32_t)((kcol >> 5) * 5120 + r * 80
                                          + (kcol & 31) * 2);
                *(uint32_t*)(sm + SM_H + off) = pack2h(z0, z1);
            }
        }

    // zero accumulators for phase B
#pragma unroll
    for (int i = 0; i < 2; i++)
#pragma unroll
        for (int j = 0; j < 8; j++)
#pragma unroll
            for (int e = 0; e < 4; e++) c[i][j][e] = 0.f;

    // =================== Phase B: acc2 = h @ Wb =========================
    cpw(Wb, 0, 0);
    CP_COMMIT();

#pragma unroll 1
    for (int ck = 0; ck < 8; ck++) {
        const int st = ck & 1;
        if (ck < 7) {
            cpw(Wb, ck + 1, st ^ 1);
            CP_COMMIT();
            CP_WAIT1();
        } else {
            CP_WAIT0();
        }
        __syncthreads();
        compute(sb + SM_H + ck * 5120, sb + SM_W(st));
        __syncthreads();
    }

    // ---- epilogue 2: LN(acc2 + bb + X) * g + beta ----
#pragma unroll
    for (int mf = 0; mf < 2; mf++)
#pragma unroll
        for (int rh = 0; rh < 2; rh++) {
            int r = wm * 32 + mf * 16 + rh * 8 + qrow;
            int grow = bm + r;
            float su = 0.f, sq = 0.f;
            if (grow < M) {
                const float* rrow = X + (size_t)grow * H;
#pragma unroll
                for (int nf = 0; nf < 8; nf++) {
                    int col = wn * 64 + nf * 8 + qcol * 2;
                    float2 rv = *(const float2*)(rrow + col);
                    float z0 = c[mf][nf][rh * 2]     + b2S[col]     + rv.x;
                    float z1 = c[mf][nf][rh * 2 + 1] + b2S[col + 1] + rv.y;
                    c[mf][nf][rh * 2]     = z0;
                    c[mf][nf][rh * 2 + 1] = z1;
                    su += z0 + z1;
                    sq += z0 * z0 + z1 * z1;
                }
            }
            su += __shfl_xor_sync(0xFFFFFFFFu, su, 1);
            su += __shfl_xor_sync(0xFFFFFFFFu, su, 2);
            sq += __shfl_xor_sync(0xFFFFFFFFu, sq, 1);
            sq += __shfl_xor_sync(0xFFFFFFFFu, sq, 2);
            if (qcol == 0 && grow < M) {
                atomicAdd(&psum[r], su);
                atomicAdd(&psq[r], sq);
            }
        }
    __syncthreads();
#pragma unroll
    for (int mf = 0; mf < 2; mf++)
#pragma unroll
        for (int rh = 0; rh < 2; rh++) {
            int r = wm * 32 + mf * 16 + rh * 8 + qrow;
            int grow = bm + r;
            if (grow >= M) continue;
            float mu = psum[r] * (1.f / 256.f);
            float var = psq[r] * (1.f / 256.f) - mu * mu;
            float rs = rsqrtf(var + LN_EPS);
            float* crow = C + (size_t)grow * H;
#pragma unroll
            for (int nf = 0; nf < 8; nf++) {
                int col = wn * 64 + nf * 8 + qcol * 2;
                float2 o;
                o.x = (c[mf][nf][rh * 2]     - mu) * rs * gS[col]     + bS[col];
                o.y = (c[mf][nf][rh * 2 + 1] - mu) * rs * gS[col + 1] + bS[col + 1];
                *(float2*)(crow + col) = o;
            }
        }
}

// ---------------------------------------------------------------------------
// launch
// ---------------------------------------------------------------------------
extern "C" void kernel_launch(void* const* d_in, const int* in_sizes, int n_in,
                              void* d_out, int out_size) {
    const float* x_var    = (const float*)d_in[0];
    const float* x_constr = (const float*)d_in[1];
    const int*   ei_v2c   = (const int*)  d_in[2];
    const int*   ei_c2v   = (const int*)  d_in[3];
    const float* ea       = (const float*)d_in[4];
    const float* We1 = (const float*)d_in[5];
    const float* be1 = (const float*)d_in[6];
    const float* W1a = (const float*)d_in[7];
    const float* b1a = (const float*)d_in[8];
    const float* W1b = (const float*)d_in[9];
    const float* b1b = (const float*)d_in[10];
    const float* We2 = (const float*)d_in[11];
    const float* be2 = (const float*)d_in[12];
    const float* W2a = (const float*)d_in[13];
    const float* b2a = (const float*)d_in[14];
    const float* W2b = (const float*)d_in[15];
    const float* b2b = (const float*)d_in[16];
    const float* g_constr    = (const float*)d_in[17];
    const float* beta_constr = (const float*)d_in[18];
    const float* g_var       = (const float*)d_in[19];
    const float* beta_var    = (const float*)d_in[20];

    const int NVr = in_sizes[0] / H;
    const int NCr = in_sizes[1] / H;
    const int Ecnt = in_sizes[4];

    float* agg;
    cudaGetSymbolAddress((void**)&agg, g_agg);
    __half* wt;
    cudaGetSymbolAddress((void**)&wt, g_wt);
    __half* wt1a = wt;
    __half* wt1b = wt + H * H;
    __half* wt2a = wt + 2 * H * H;
    __half* wt2b = wt + 3 * H * H;

    cudaFuncSetAttribute(fused_gine,
                         cudaFuncAttributeMaxDynamicSharedMemorySize, SMEM_T);

    float* out_var    = (float*)d_out;
    float* out_constr = (float*)d_out + (size_t)NVr * H;

    const int edge_blocks = (Ecnt + 3) / 4;

    // weight prep: all 4 weights (order: W1a, W1b, W2a, W2b)
    wprep4_kernel<<<256, 256>>>(W1a, W1b, W2a, W2b, wt);

    // ---- stage 1: var -> constr ----
    {
        int n4 = NCr * H / 4;
        zero_kernel<<<(n4 + 255) / 256, 256>>>((float4*)agg, n4);
        edge_scatter_kernel<<<edge_blocks, 256>>>(x_var, ei_v2c, ei_v2c + Ecnt,
                                                  ea, We1, be1, agg, Ecnt);
        int gx = (NCr + 63) / 64;
        fused_gine<<<gx, 256, SMEM_T>>>(
            x_constr, agg, wt1a, wt1b, b1a, b1b,
            g_constr, beta_constr, out_constr, NCr);
    }

    // ---- stage 2: constr -> var (reads LN'd x_constr from d_out) ----
    {
        int n4 = NVr * H / 4;
        zero_kernel<<<(n4 + 255) / 256, 256>>>((float4*)agg, n4);
        edge_scatter_kernel<<<edge_blocks, 256>>>(out_constr, ei_c2v, ei_c2v + Ecnt,
                                                  ea, We2, be2, agg, Ecnt);
        int gx = (NVr + 63) / 64;
        fused_gine<<<gx, 256, SMEM_T>>>(
            x_var, agg, wt2a, wt2b, b2a, b2b,
            g_var, beta_var, out_var, NVr);
    }
}